// round 9
// baseline (speedup 1.0000x reference)
#include <cuda_runtime.h>
#include <cuda_bf16.h>
#include <math.h>

#define BATCH  8192
#define NNZ    32
#define FT_IN  40960
#define FT_OUT 512
#define ROWS_PER_CTA 2
#define NTHREADS 256   // 128 threads per batch row: 64 stm + 64 nstm, 8 cols each
#define FOLD 8         // bf16 accumulation depth before folding into f32

// 40 MB bf16 copy of the feature table (static device scratch — no runtime alloc)
__device__ __nv_bfloat16 g_wft[FT_IN * FT_OUT];

// ---------------- Kernel 1: f32 -> bf16 table conversion (streaming) -------------
__global__ __launch_bounds__(256)
void convert_kernel(const float4* __restrict__ W_ft)
{
    const int i = blockIdx.x * 256 + threadIdx.x;   // group of 8 floats
    const float4 a = __ldcs(&W_ft[2 * i]);
    const float4 b = __ldcs(&W_ft[2 * i + 1]);
    __nv_bfloat162 p0 = __floats2bfloat162_rn(a.x, a.y);
    __nv_bfloat162 p1 = __floats2bfloat162_rn(a.z, a.w);
    __nv_bfloat162 p2 = __floats2bfloat162_rn(b.x, b.y);
    __nv_bfloat162 p3 = __floats2bfloat162_rn(b.z, b.w);
    uint4 o;
    o.x = *(unsigned*)&p0;  o.y = *(unsigned*)&p1;
    o.z = *(unsigned*)&p2;  o.w = *(unsigned*)&p3;
    ((uint4*)g_wft)[i] = o;
}

// f32 view of packed bf16 pair: low elem = shift; high elem = raw word (junk low
// mantissa bits perturb by <2^-8 relative — same order as bf16 rounding itself)
__device__ __forceinline__ float bf_lo(__nv_bfloat162 a) {
    unsigned w = *(unsigned*)&a;  return __int_as_float((int)(w << 16));
}
__device__ __forceinline__ float bf_hi(__nv_bfloat162 a) {
    unsigned w = *(unsigned*)&a;  return __uint_as_float(w);
}
__device__ __forceinline__ __nv_bfloat162 bf2_zero() {
    unsigned z = 0u;  return *(__nv_bfloat162*)&z;
}

// ---------------- Kernel 2: sparse gather + MLP head from bf16 table -------------
__global__ __launch_bounds__(NTHREADS)
void nnue_fwd_kernel(const int*    __restrict__ stm_idx,    // [BATCH, NNZ]
                     const int*    __restrict__ nstm_idx,   // [BATCH, NNZ]
                     const float*  __restrict__ values,     // [BATCH, NNZ]
                     const float4* __restrict__ b_ft,       // [FT_OUT]
                     const float4* __restrict__ W_out,      // [2*FT_OUT]
                     const float*  __restrict__ b_out,      // [1]
                     float*        __restrict__ out)        // [BATCH]
{
    const int t    = threadIdx.x;
    const int r    = t >> 7;               // row within CTA (0/1)
    const int lt   = t & 127;              // lane within row group
    const int half = lt >> 6;              // 0 = stm, 1 = nstm
    const int c    = lt & 63;              // uint4 (8-col) slot 0..63
    const int b    = blockIdx.x * ROWS_PER_CTA + r;

    // packed per-k record: {row offset in uint4 units, value as splat bf16x2}
    __shared__ int2  s_ov[ROWS_PER_CTA][2 * NNZ];
    __shared__ float s_red[NTHREADS / 32];

    if (lt < NNZ) {
        const float v = __ldcs(&values[b * NNZ + lt]);
        __nv_bfloat162 vv = __bfloat162bfloat162(__float2bfloat16(v));
        const int vv_bits = *(int*)&vv;
        s_ov[r][lt]       = make_int2(__ldcs(&stm_idx [b * NNZ + lt]) * (FT_OUT / 8), vv_bits);
        s_ov[r][NNZ + lt] = make_int2(__ldcs(&nstm_idx[b * NNZ + lt]) * (FT_OUT / 8), vv_bits);
    }
    __syncthreads();

    const int2*  my  = &s_ov[r][half * NNZ];
    const uint4* tab = (const uint4*)g_wft + c;    // row stride = FT_OUT/8 uint4

    float m[8] = {0.f, 0.f, 0.f, 0.f, 0.f, 0.f, 0.f, 0.f};

    #pragma unroll
    for (int g = 0; g < NNZ / FOLD; g++) {
        __nv_bfloat162 a0 = bf2_zero();
        __nv_bfloat162 a1 = a0, a2 = a0, a3 = a0;
        #pragma unroll
        for (int kk = 0; kk < FOLD; kk++) {
            const int2 ov = my[g * FOLD + kk];
            const uint4 w = __ldg(tab + ov.x);
            const __nv_bfloat162 vv = *(const __nv_bfloat162*)&ov.y;
            a0 = __hfma2(*(const __nv_bfloat162*)&w.x, vv, a0);
            a1 = __hfma2(*(const __nv_bfloat162*)&w.y, vv, a1);
            a2 = __hfma2(*(const __nv_bfloat162*)&w.z, vv, a2);
            a3 = __hfma2(*(const __nv_bfloat162*)&w.w, vv, a3);
        }
        // fold bf16 partial sums into f32 masters (caps bf16 depth at FOLD)
        m[0] += bf_lo(a0);  m[1] += bf_hi(a0);
        m[2] += bf_lo(a1);  m[3] += bf_hi(a1);
        m[4] += bf_lo(a2);  m[5] += bf_hi(a2);
        m[6] += bf_lo(a3);  m[7] += bf_hi(a3);
    }

    // bias + clamp [0,1] + dot with matching W_out half (hidden = [stm | nstm])
    const float4 bb0 = __ldg(&b_ft[2 * c]);
    const float4 bb1 = __ldg(&b_ft[2 * c + 1]);
    const float4 wo0 = __ldg(&W_out[half * (FT_OUT / 4) + 2 * c]);
    const float4 wo1 = __ldg(&W_out[half * (FT_OUT / 4) + 2 * c + 1]);
    const float bbv[8] = {bb0.x, bb0.y, bb0.z, bb0.w, bb1.x, bb1.y, bb1.z, bb1.w};
    const float wov[8] = {wo0.x, wo0.y, wo0.z, wo0.w, wo1.x, wo1.y, wo1.z, wo1.w};
    float p = 0.f;
    #pragma unroll
    for (int i = 0; i < 8; i++) {
        const float h = fminf(fmaxf(m[i] + bbv[i], 0.f), 1.f);
        p = fmaf(h, wov[i], p);
    }

    // warp reduce (each warp = 32 threads of one half-row slice)
    #pragma unroll
    for (int off = 16; off > 0; off >>= 1)
        p += __shfl_xor_sync(0xFFFFFFFFu, p, off);

    if ((t & 31) == 0) s_red[t >> 5] = p;
    __syncthreads();

    // warps 0-3 belong to row 0, warps 4-7 to row 1
    if ((t & 127) == 0) {
        const int w0 = r * 4;
        float s = s_red[w0] + s_red[w0 + 1] + s_red[w0 + 2] + s_red[w0 + 3]
                + __ldg(b_out);
        out[b] = 1.0f / (1.0f + expf(-s));
    }
}

extern "C" void kernel_launch(void* const* d_in, const int* in_sizes, int n_in,
                              void* d_out, int out_size)
{
    const int*    stm_idx  = (const int*)   d_in[0];
    const int*    nstm_idx = (const int*)   d_in[1];
    const float*  values   = (const float*) d_in[2];
    const float4* W_ft     = (const float4*)d_in[3];
    const float4* b_ft     = (const float4*)d_in[4];
    const float4* W_out    = (const float4*)d_in[5];
    const float*  b_out    = (const float*) d_in[6];
    float*        out      = (float*)       d_out;

    // 20,971,520 floats / 8 per thread / 256 threads = 10240 blocks
    convert_kernel<<<(FT_IN * FT_OUT) / (8 * 256), 256>>>(W_ft);
    nnue_fwd_kernel<<<BATCH / ROWS_PER_CTA, NTHREADS>>>(stm_idx, nstm_idx, values,
                                                        b_ft, W_out, b_out, out);
}